// round 8
// baseline (speedup 1.0000x reference)
#include <cuda_runtime.h>
#include <cuda_bf16.h>
#include <cstdint>

#define BH     64
#define SEQ    8192
#define DIM    64
#define NCHUNK 32
#define CHUNK  (SEQ / NCHUNK)   // 256
#define TS     16
#define NT     (CHUNK / TS)     // 16

typedef unsigned long long u64;

// Scratch (allocation-free: __device__ globals)
__device__ float g_kv_part[BH * NCHUNK * DIM * DIM];  // 32 MB
__device__ float g_ks_part[BH * NCHUNK * DIM];
__device__ float g_kvT[BH * 72 * DIM];   // [e(64)+ksum(1)+pad(7)][d(64)]  (tensor B)
__device__ float g_kv [BH * DIM * DIM];  // [d][e]                         (fma path)
__device__ float g_ks [BH * DIM];

// ---- packed f32x2 helpers ---------------------------------------------------
__device__ __forceinline__ u64 pack2(float lo, float hi) {
    u64 r;
    asm("mov.b64 %0, {%1, %2};" : "=l"(r) : "f"(lo), "f"(hi));
    return r;
}
__device__ __forceinline__ void unpack2(u64 v, float& lo, float& hi) {
    asm("mov.b64 {%0, %1}, %2;" : "=f"(lo), "=f"(hi) : "l"(v));
}
__device__ __forceinline__ void fma2(u64& d, u64 a, u64 b) {
    asm("fma.rn.f32x2 %0, %1, %2, %0;" : "+l"(d) : "l"(a), "l"(b));
}
// ---- cp.async helpers --------------------------------------------------------
__device__ __forceinline__ void cp16(void* s, const void* g) {
    uint32_t sa = (uint32_t)__cvta_generic_to_shared(s);
    asm volatile("cp.async.cg.shared.global [%0], [%1], 16;"
                 :: "r"(sa), "l"(g) : "memory");
}
#define CP_COMMIT() asm volatile("cp.async.commit_group;" ::: "memory")
#define CP_WAIT1()  asm volatile("cp.async.wait_group 1;" ::: "memory")

// swizzled column for fma-path kv smem
__device__ __forceinline__ int swz(int e) { return e + ((e >> 5) << 2); }

// ---------------------------------------------------------------------------
// Phase 1 (unchanged, measured best): partial kv = relu(K)^T @ V, ksum.
// ---------------------------------------------------------------------------
__global__ __launch_bounds__(64) void la_phase1(const float* __restrict__ K,
                                                const float* __restrict__ V) {
    const int bh = blockIdx.x, chunk = blockIdx.y;
    const float* Kh = K + (size_t)bh * SEQ * DIM + (size_t)chunk * CHUNK * DIM;
    const float* Vh = V + (size_t)bh * SEQ * DIM + (size_t)chunk * CHUNK * DIM;

    __shared__ float Ks[2][TS][DIM];
    __shared__ float Vs[2][TS][DIM];

    const int t  = threadIdx.x;
    const int tx = t & 7;
    const int ty = t >> 3;

    int crow[4], ccol[4];
#pragma unroll
    for (int l = 0; l < 4; l++) {
        int idx = l * 64 + t;
        crow[l] = idx >> 4;
        ccol[l] = (idx & 15) * 4;
    }

    u64 acc[8][4];
    float ksum[8];
#pragma unroll
    for (int i = 0; i < 8; i++) {
        ksum[i] = 0.f;
#pragma unroll
        for (int j = 0; j < 4; j++) acc[i][j] = 0ull;
    }

#pragma unroll
    for (int p = 0; p < 2; p++) {
#pragma unroll
        for (int l = 0; l < 4; l++) {
            cp16(&Ks[p][crow[l]][ccol[l]],
                 Kh + (size_t)(p * TS + crow[l]) * DIM + ccol[l]);
            cp16(&Vs[p][crow[l]][ccol[l]],
                 Vh + (size_t)(p * TS + crow[l]) * DIM + ccol[l]);
        }
        CP_COMMIT();
    }

    for (int tl = 0; tl < NT; tl++) {
        CP_WAIT1();
        __syncthreads();
        const int b = tl & 1;

#pragma unroll 8
        for (int s = 0; s < TS; s++) {
            float4 ka = *(const float4*)&Ks[b][s][ty * 8];
            float4 kb = *(const float4*)&Ks[b][s][ty * 8 + 4];
            ulonglong2 va = *(const ulonglong2*)&Vs[b][s][tx * 8];
            ulonglong2 vb = *(const ulonglong2*)&Vs[b][s][tx * 8 + 4];
            float kf[8] = {ka.x, ka.y, ka.z, ka.w, kb.x, kb.y, kb.z, kb.w};
#pragma unroll
            for (int i = 0; i < 8; i++) {
                float km = fmaxf(kf[i], 0.f);
                ksum[i] += km;
                u64 k2 = pack2(km, km);
                fma2(acc[i][0], k2, va.x);
                fma2(acc[i][1], k2, va.y);
                fma2(acc[i][2], k2, vb.x);
                fma2(acc[i][3], k2, vb.y);
            }
        }
        __syncthreads();

        if (tl + 2 < NT) {
#pragma unroll
            for (int l = 0; l < 4; l++) {
                cp16(&Ks[b][crow[l]][ccol[l]],
                     Kh + (size_t)((tl + 2) * TS + crow[l]) * DIM + ccol[l]);
                cp16(&Vs[b][crow[l]][ccol[l]],
                     Vh + (size_t)((tl + 2) * TS + crow[l]) * DIM + ccol[l]);
            }
        }
        CP_COMMIT();
    }

    float* kvp = g_kv_part + ((size_t)bh * NCHUNK + chunk) * DIM * DIM;
#pragma unroll
    for (int i = 0; i < 8; i++) {
        int d = ty * 8 + i;
        float o0, o1, o2, o3, o4, o5, o6, o7;
        unpack2(acc[i][0], o0, o1);
        unpack2(acc[i][1], o2, o3);
        unpack2(acc[i][2], o4, o5);
        unpack2(acc[i][3], o6, o7);
        *(float4*)&kvp[d * DIM + tx * 8]     = make_float4(o0, o1, o2, o3);
        *(float4*)&kvp[d * DIM + tx * 8 + 4] = make_float4(o4, o5, o6, o7);
    }
    if (tx == 0) {
#pragma unroll
        for (int i = 0; i < 8; i++)
            g_ks_part[((size_t)bh * NCHUNK + chunk) * DIM + ty * 8 + i] = ksum[i];
    }
}

// ---------------------------------------------------------------------------
// Reduce partials -> g_kvT (tensor B layout), g_kv ([d][e]), g_ks
// ---------------------------------------------------------------------------
__global__ __launch_bounds__(256) void la_reduce() {
    const int bh  = blockIdx.x;
    const int tid = threadIdx.x;
    float* outT = g_kvT + (size_t)bh * 72 * DIM;
    float* outN = g_kv  + (size_t)bh * DIM * DIM;
    for (int idx = tid; idx < DIM * DIM; idx += 256) {
        int d = idx >> 6, e = idx & 63;
        float sum = 0.f;
#pragma unroll
        for (int c = 0; c < NCHUNK; c++)
            sum += g_kv_part[((size_t)bh * NCHUNK + c) * DIM * DIM + idx];
        outT[e * DIM + d] = sum;
        outN[idx] = sum;
    }
    if (tid < DIM) {
        float s = 0.f;
#pragma unroll
        for (int c = 0; c < NCHUNK; c++)
            s += g_ks_part[((size_t)bh * NCHUNK + c) * DIM + tid];
        outT[64 * DIM + tid] = s;
        g_ks[bh * DIM + tid] = s;
    }
    for (int i = tid; i < 7 * DIM; i += 256)
        outT[65 * DIM + i] = 0.f;
}

// ===========================================================================
// Phase 2 HYBRID: 384 threads per CTA, 192 rows per block.
//   warps 0-7  : HMMA (R5-proven) on rows [row0, row0+128), tensor pipe
//   warps 8-11 : f32x2 (R2-proven) on rows [row0+128, row0+192), fma pipe
// Both pipes run concurrently on every SM. Last block (row0=8064) tensor-only.
// ===========================================================================
#define KPAD2 136
#define SM_A    0
#define SM_B    34816                       // A: 128*136*2
#define SM_KV   54400                       // B: 72*136*2
#define SM_QS   71808                       // kv: 64*68*4
#define SM_KS   81024                       // qs: 64*36*4
#define P2_SMEM 81664                       // kss: 130*4 -> 81544, pad

__device__ __forceinline__ uint32_t pack_bf2(__nv_bfloat16 lo, __nv_bfloat16 hi) {
    __nv_bfloat162 t = __halves2bfloat162(lo, hi);
    return *(uint32_t*)&t;
}

__global__ __launch_bounds__(384, 2) void la_phase2(const float* __restrict__ Q,
                                                    float* __restrict__ O) {
    extern __shared__ char sm[];
    __nv_bfloat16* As = (__nv_bfloat16*)(sm + SM_A);
    __nv_bfloat16* Bs = (__nv_bfloat16*)(sm + SM_B);
    float* kvs  = (float*)(sm + SM_KV);    // [64][68] swizzled
    float* qs   = (float*)(sm + SM_QS);    // [64][36] dup'd relu(Q), per pass
    float* kssd = (float*)(sm + SM_KS);    // [130] dup'd ksum

    const int bh   = blockIdx.x;
    const int row0 = blockIdx.y * 192;
    const float* Qh = Q + (size_t)bh * SEQ * DIM + (size_t)row0 * DIM;

    const int tid  = threadIdx.x;
    const int lane = tid & 31;
    const int wid  = tid >> 5;

    // ======== joint staging (all 384 threads) ========
    // A = relu(Q) rows row0..row0+127, [hi|lo] bf16
    for (int idx = tid; idx < 2048; idx += 384) {
        int m = idx >> 4;
        int k = (idx & 15) * 4;
        float4 q = *(const float4*)(Qh + (size_t)m * DIM + k);
        q.x = fmaxf(q.x, 0.f); q.y = fmaxf(q.y, 0.f);
        q.z = fmaxf(q.z, 0.f); q.w = fmaxf(q.w, 0.f);
        __nv_bfloat16 hx = __float2bfloat16_rn(q.x), hy = __float2bfloat16_rn(q.y);
        __nv_bfloat16 hz = __float2bfloat16_rn(q.z), hw = __float2bfloat16_rn(q.w);
        __nv_bfloat16 lx = __float2bfloat16_rn(q.x - __bfloat162float(hx));
        __nv_bfloat16 ly = __float2bfloat16_rn(q.y - __bfloat162float(hy));
        __nv_bfloat16 lz = __float2bfloat16_rn(q.z - __bfloat162float(hz));
        __nv_bfloat16 lw = __float2bfloat16_rn(q.w - __bfloat162float(hw));
        __nv_bfloat16* row = As + (size_t)m * KPAD2;
        *(uint2*)(row + k)      = make_uint2(pack_bf2(hx, hy), pack_bf2(hz, hw));
        *(uint2*)(row + 64 + k) = make_uint2(pack_bf2(lx, ly), pack_bf2(lz, lw));
    }
    // B = g_kvT [hi|lo]
    const float* Bg = g_kvT + (size_t)bh * 72 * DIM;
    for (int idx = tid; idx < 72 * 16; idx += 384) {
        int n = idx >> 4;
        int k = (idx & 15) * 4;
        float4 b = *(const float4*)(Bg + (size_t)n * DIM + k);
        __nv_bfloat16 hx = __float2bfloat16_rn(b.x), hy = __float2bfloat16_rn(b.y);
        __nv_bfloat16 hz = __float2bfloat16_rn(b.z), hw = __float2bfloat16_rn(b.w);
        __nv_bfloat16 lx = __float2bfloat16_rn(b.x - __bfloat162float(hx));
        __nv_bfloat16 ly = __float2bfloat16_rn(b.y - __bfloat162float(hy));
        __nv_bfloat16 lz = __float2bfloat16_rn(b.z - __bfloat162float(hz));
        __nv_bfloat16 lw = __float2bfloat16_rn(b.w - __bfloat162float(hw));
        __nv_bfloat16* row = Bs + (size_t)n * KPAD2;
        *(uint2*)(row + k)      = make_uint2(pack_bf2(hx, hy), pack_bf2(hz, hw));
        *(uint2*)(row + 64 + k) = make_uint2(pack_bf2(lx, ly), pack_bf2(lz, lw));
    }
    // kv fp32 (swizzled) + dup'd ksum for the fma warps
    const float4* kvg = (const float4*)(g_kv + (size_t)bh * DIM * DIM);
    for (int idx = tid; idx < 1024; idx += 384) {
        int r  = idx >> 4;
        int c4 = idx & 15;
        *(float4*)&kvs[r * 68 + swz(c4 * 4)] = kvg[idx];
    }
    if (tid < DIM) {
        float s = g_ks[bh * DIM + tid];
        kssd[2 * tid] = s; kssd[2 * tid + 1] = s;
    }
    __syncthreads();

    if (wid < 8) {
        // ================= TENSOR path (R5-proven) =================
        const int m0 = wid * 16;
        uint32_t Abase = (uint32_t)__cvta_generic_to_shared(As);
        uint32_t Bbase = (uint32_t)__cvta_generic_to_shared(Bs);
        uint32_t aAddr = Abase + (uint32_t)(m0 + (lane & 15)) * (KPAD2 * 2)
                       + (uint32_t)(lane >> 4) * 16;
        uint32_t bAddr = Bbase + (uint32_t)(lane & 7) * (KPAD2 * 2)
                       + (uint32_t)((lane >> 3) & 1) * 16;

        constexpr int aOffs[12] = {0,32,64,96, 0,32,64,96, 128,160,192,224};
        constexpr int bOffs[12] = {0,32,64,96, 128,160,192,224, 0,32,64,96};

        float acc[9][4];
#pragma unroll
        for (int j = 0; j < 9; j++)
#pragma unroll
            for (int r = 0; r < 4; r++) acc[j][r] = 0.f;

#pragma unroll
        for (int ks = 0; ks < 12; ks++) {
            uint32_t a0, a1, a2, a3;
            asm volatile("ldmatrix.sync.aligned.m8n8.x4.shared.b16 {%0,%1,%2,%3}, [%4];"
                         : "=r"(a0), "=r"(a1), "=r"(a2), "=r"(a3)
                         : "r"(aAddr + aOffs[ks]));
#pragma unroll
            for (int j = 0; j < 9; j++) {
                uint32_t b0, b1;
                asm volatile("ldmatrix.sync.aligned.m8n8.x2.shared.b16 {%0,%1}, [%2];"
                             : "=r"(b0), "=r"(b1)
                             : "r"(bAddr + j * (8 * KPAD2 * 2) + bOffs[ks]));
                asm volatile(
                    "mma.sync.aligned.m16n8k16.row.col.f32.bf16.bf16.f32 "
                    "{%0,%1,%2,%3}, {%4,%5,%6,%7}, {%8,%9}, {%0,%1,%2,%3};"
                    : "+f"(acc[j][0]), "+f"(acc[j][1]), "+f"(acc[j][2]), "+f"(acc[j][3])
                    : "r"(a0), "r"(a1), "r"(a2), "r"(a3), "r"(b0), "r"(b1));
            }
        }

        const int g = lane >> 2;
        float nlo = __shfl_sync(0xffffffffu, acc[8][0], lane & ~3);
        float nhi = __shfl_sync(0xffffffffu, acc[8][2], lane & ~3);
        float ilo = 1.f / fmaxf(nlo, 1e-6f);
        float ihi = 1.f / fmaxf(nhi, 1e-6f);

        float* O0 = O + ((size_t)bh * SEQ + row0 + m0 + g) * DIM + 2 * (lane & 3);
        float* O1 = O0 + 8 * DIM;
#pragma unroll
        for (int j = 0; j < 8; j++) {
            *(float2*)(O0 + j * 8) = make_float2(acc[j][0] * ilo, acc[j][1] * ilo);
            *(float2*)(O1 + j * 8) = make_float2(acc[j][2] * ihi, acc[j][3] * ihi);
        }
    } else if (row0 + 128 < SEQ) {
        // ================= FMA path (R2-proven), rows row0+128..+191 ========
        const int wtid = tid - 256;        // 0..127
        const int tx = wtid & 7;
        const int ty = wtid >> 3;          // 0..15
        const int kc = swz(tx * 8);
        const float* Qf = Qh + (size_t)128 * DIM;
        float* Of = O + ((size_t)bh * SEQ + row0 + 128) * DIM;

        u64 acc[4][4];
        u64 nrm2[4];
#pragma unroll
        for (int i = 0; i < 4; i++) {
            nrm2[i] = 0ull;
#pragma unroll
            for (int j = 0; j < 4; j++) acc[i][j] = 0ull;
        }

        for (int pass = 0; pass < 4; pass++) {
            asm volatile("bar.sync 15, 128;" ::: "memory");
            // stage relu(Q) dup'd, cols [pass*16, +16): 256 float4 / 128 thr
#pragma unroll
            for (int l = 0; l < 2; l++) {
                int idx = l * 128 + wtid;
                int row = idx >> 2;
                int cg  = idx & 3;
                float4 q = *(const float4*)(Qf + (size_t)row * DIM + pass * 16 + cg * 4);
                q.x = fmaxf(q.x, 0.f); q.y = fmaxf(q.y, 0.f);
                q.z = fmaxf(q.z, 0.f); q.w = fmaxf(q.w, 0.f);
                *(float4*)&qs[row * 36 + cg * 8]     = make_float4(q.x, q.x, q.y, q.y);
                *(float4*)&qs[row * 36 + cg * 8 + 4] = make_float4(q.z, q.z, q.w, q.w);
            }
            asm volatile("bar.sync 15, 128;" ::: "memory");

#pragma unroll
            for (int p = 0; p < 8; p++) {
                const int d0 = pass * 16 + 2 * p;
                u64 ks0 = *(const u64*)&kssd[2 * d0];
                u64 ks1 = *(const u64*)&kssd[2 * d0 + 2];
                ulonglong2 a_lo = *(const ulonglong2*)&kvs[d0 * 68 + kc];
                ulonglong2 a_hi = *(const ulonglong2*)&kvs[d0 * 68 + kc + 4];
                ulonglong2 b_lo = *(const ulonglong2*)&kvs[(d0 + 1) * 68 + kc];
                ulonglong2 b_hi = *(const ulonglong2*)&kvs[(d0 + 1) * 68 + kc + 4];
#pragma unroll
                for (int i = 0; i < 4; i++) {
                    ulonglong2 qd = *(const ulonglong2*)&qs[(ty * 4 + i) * 36 + p * 4];
                    fma2(nrm2[i], qd.x, ks0);
                    fma2(nrm2[i], qd.y, ks1);
                    fma2(acc[i][0], qd.x, a_lo.x); fma2(acc[i][1], qd.x, a_lo.y);
                    fma2(acc[i][2], qd.x, a_hi.x); fma2(acc[i][3], qd.x, a_hi.y);
                    fma2(acc[i][0], qd.y, b_lo.x); fma2(acc[i][1], qd.y, b_lo.y);
                    fma2(acc[i][2], qd.y, b_hi.x); fma2(acc[i][3], qd.y, b_hi.y);
                }
            }
        }

#pragma unroll
        for (int i = 0; i < 4; i++) {
            float nl, nh;
            unpack2(nrm2[i], nl, nh);
            float inv = 1.f / fmaxf(nl, 1e-6f);
            float o0, o1, o2, o3, o4, o5, o6, o7;
            unpack2(acc[i][0], o0, o1);
            unpack2(acc[i][1], o2, o3);
            unpack2(acc[i][2], o4, o5);
            unpack2(acc[i][3], o6, o7);
            int row = ty * 4 + i;
            *(float4*)&Of[(size_t)row * DIM + tx * 8] =
                make_float4(o0 * inv, o1 * inv, o2 * inv, o3 * inv);
            *(float4*)&Of[(size_t)row * DIM + tx * 8 + 4] =
                make_float4(o4 * inv, o5 * inv, o6 * inv, o7 * inv);
        }
    }
}

// ---------------------------------------------------------------------------
extern "C" void kernel_launch(void* const* d_in, const int* in_sizes, int n_in,
                              void* d_out, int out_size) {
    const float* q = (const float*)d_in[0];
    const float* k = (const float*)d_in[1];
    const float* v = (const float*)d_in[2];
    float* o = (float*)d_out;

    static bool configured = false;
    if (!configured) {
        cudaFuncSetAttribute(la_phase2, cudaFuncAttributeMaxDynamicSharedMemorySize,
                             P2_SMEM);
        configured = true;
    }

    la_phase1<<<dim3(BH, NCHUNK), 64>>>(k, v);
    la_reduce<<<BH, 256>>>();
    la_phase2<<<dim3(BH, (SEQ + 191) / 192), 384, P2_SMEM>>>(q, o);
}